// round 4
// baseline (speedup 1.0000x reference)
#include <cuda_runtime.h>
#include <cstdint>

#define HH 19
#define CELLS 361
#define MASK19 0x7FFFFu
#define BPB 4
#define NT 256                          // 8 warps
#define NIN (BPB * 722)                 // 2888 input floats / block
#define NBITW 96                        // ballot words (covers k*8+wid, max 95)
#define ONEF 0x3F800000u

// bit c of m, as float-1.0 bit pattern
__device__ __forceinline__ uint32_t bitf1(uint32_t m, int c) {
    return (uint32_t)(((int32_t)(m << (31 - c))) >> 31) & ONEF;
}

__global__ __launch_bounds__(NT, 8)
void go_feat_kernel(const float* __restrict__ stones,
                    const int*   __restrict__ cur_player,
                    const int*   __restrict__ ko_points,
                    float*       __restrict__ out,
                    int B)
{
    __shared__ uint32_t s_bits[NBITW + 1];          // +1 pad for funnel hi word
    __shared__ uint32_t s_cur [BPB][21];            // padded row masks
    __shared__ uint32_t s_opp [BPB][21];
    __shared__ uint32_t s_emp [BPB][21];
    __shared__ uint32_t s_weak[BPB][21];
    __shared__ int      s_cp[BPB];
    __shared__ float    s_turn[BPB];
    __shared__ int      s_ko[BPB][2];
    __shared__ float    s_stage[BPB * 722];         // ch2 + ch3, 11552 B

    const int t     = threadIdx.x;
    const int bbase = blockIdx.x * BPB;
    const int rb    = (B - bbase) < BPB ? (B - bbase) : BPB;
    const int nin   = rb * 722;

    // ---------------- preload per-board scalars ----------------
    if (t < BPB) {
        const bool ok = t < rb;
        const int  b  = bbase + (ok ? t : 0);
        const int  cp = ok ? cur_player[b] : 0;
        s_cp[t]   = cp;
        s_turn[t] = (float)cp;
        s_ko[t][0] = ok ? ko_points[2 * b]     : -1;
        s_ko[t][1] = ok ? ko_points[2 * b + 1] : 0;
    }
    __syncthreads();

    // ---------------- Phase A: fused input pass ----------------
    // coalesced LDG -> (a) direct copy to out ch0/ch1 (plane-swapped by cp)
    //                  (b) ballot-pack into 722-bit-per-board bitstream
    const float* src  = stones + (size_t)bbase * 722;
    float*       outb = out    + (size_t)bbase * 1805;

#pragma unroll
    for (int k = 0; k < 12; ++k) {                  // 12*256 = 3072 >= 2888
        const int i = k * NT + t;
        const bool act = i < nin;
        float v = 0.0f;
        if (act) v = src[i];
        const unsigned bal = __ballot_sync(0xFFFFFFFFu, act && (v > 0.5f));
        if ((t & 31) == 0)
            s_bits[k * 8 + (t >> 5)] = bal;         // each (k,warp) -> unique word
        if (act) {
            const int lb   = i / 722;
            const int j    = i - 722 * lb;
            const int p    = (j >= 361);
            const int cell = j - (p ? 361 : 0);
            const int q    = p ^ s_cp[lb];          // out plane
            outb[lb * 1805 + q * 361 + cell] = v;
        }
    }
    if (t == 0) s_bits[NBITW] = 0u;
    __syncthreads();

    // ---------------- Phase 1: extract row masks (funnel shift) ----------------
    if (t < BPB * HH) {                             // 76 threads
        const int lb = t / HH, r = t % HH;
        if (lb < rb) {
            const int bit0 = lb * 722 + r * HH;     // plane 0 row
            const int bit1 = bit0 + 361;            // plane 1 row
            const uint32_t m0 = __funnelshift_r(s_bits[bit0 >> 5],
                                                s_bits[(bit0 >> 5) + 1],
                                                bit0 & 31) & MASK19;
            const uint32_t m1 = __funnelshift_r(s_bits[bit1 >> 5],
                                                s_bits[(bit1 >> 5) + 1],
                                                bit1 & 31) & MASK19;
            const int cp = s_cp[lb];
            s_cur[lb][r + 1] = cp ? m1 : m0;
            s_opp[lb][r + 1] = cp ? m0 : m1;
            s_emp[lb][r + 1] = (~(m0 | m1)) & MASK19;
            if (r == 0) {
                s_cur [lb][0] = 0u; s_cur [lb][20] = 0u;
                s_opp [lb][0] = 0u; s_opp [lb][20] = 0u;
                s_emp [lb][0] = 0u; s_emp [lb][20] = 0u;
                s_weak[lb][0] = 0u; s_weak[lb][20] = 0u;
            }
        }
    }
    __syncthreads();

    // ---------------- Phase 2: weak = opp with exactly 1 opp neighbor ----------
    if (t < BPB * HH) {
        const int lb = t / HH, r = t % HH;
        if (lb < rb) {
            const uint32_t o   = s_opp[lb][r + 1];
            const uint32_t ou  = s_opp[lb][r];
            const uint32_t od  = s_opp[lb][r + 2];
            const uint32_t ol  = (o << 1) & MASK19;
            const uint32_t orr = o >> 1;
            const uint32_t par = ou ^ od ^ ol ^ orr;
            const uint32_t ge2 = (ou & od) | (ol & orr) | ((ou | od) & (ol | orr));
            s_weak[lb][r + 1] = o & par & ~ge2;
        }
    }
    __syncthreads();

    // ---------------- Phase 3: legal (ch2) + cur_lib (ch3) -> stage -------------
    if (t < 2 * BPB * HH) {                         // 152 threads
        const int ch = t / (BPB * HH);              // 0 -> legal, 1 -> lib
        const int w  = t % (BPB * HH);
        const int lb = w / HH, r = w % HH;
        if (lb < rb) {
            float* o = s_stage + lb * 722 + ch * CELLS + r * HH;
            if (ch == 0) {
                const uint32_t empb = s_emp[lb][r + 1];
                const uint32_t eu = s_emp [lb][r], ed = s_emp [lb][r + 2];
                const uint32_t wk = s_weak[lb][r + 1];
                const uint32_t wu = s_weak[lb][r], wd = s_weak[lb][r + 2];
                const uint32_t nbr = eu | ed | ((empb << 1) & MASK19) | (empb >> 1)
                                   | wu | wd | ((wk  << 1) & MASK19) | (wk  >> 1);
                uint32_t legal = empb & nbr;
                const int kr = s_ko[lb][0];
                if (kr >= 0) {
                    const int rr = kr > (HH - 1) ? (HH - 1) : kr;
                    int cc = s_ko[lb][1];
                    cc = cc < 0 ? 0 : (cc > (HH - 1) ? (HH - 1) : cc);
                    if (rr == r) legal &= ~(1u << cc);
                }
#pragma unroll
                for (int c = 0; c < HH; ++c)
                    o[c] = __uint_as_float(bitf1(legal, c));
            } else {
                // carry-save 4-neighbor count of cur, gated by empty
                const uint32_t curb = s_cur[lb][r + 1];
                const uint32_t cu   = s_cur[lb][r];
                const uint32_t cd   = s_cur[lb][r + 2];
                const uint32_t cl   = (curb << 1) & MASK19;
                const uint32_t crr  = curb >> 1;
                const uint32_t empb = s_emp[lb][r + 1];
                const uint32_t sab = cu ^ cd,  cab = cu & cd;
                const uint32_t scd = cl ^ crr, ccd = cl & crr;
                const uint32_t kk  = sab & scd;
                const uint32_t b0 = (sab ^ scd)      & empb;
                const uint32_t b1 = (cab ^ ccd ^ kk) & empb;
                const uint32_t b2 = (cab & ccd)      & empb;
#pragma unroll
                for (int c = 0; c < HH; ++c) {
                    const uint32_t n = ((b0 >> c) & 1u)
                                     | (((b1 >> c) & 1u) << 1)
                                     | (((b2 >> c) & 1u) << 2);
                    o[c] = (float)n;
                }
            }
        }
    }
    __syncthreads();

    // ---------------- Phase 4: coalesced stores of ch2/ch3 and ch4 --------------
    const int n2 = rb * 722;
    for (int w = t; w < n2; w += NT) {
        const int lb = w / 722;
        outb[w + lb * 1083 + 722] = s_stage[w];     // = lb*1805 + 722 + (w - 722*lb)
    }
    const int n4 = rb * CELLS;
    for (int w = t; w < n4; w += NT) {
        const int lb = w / CELLS;
        outb[w + lb * 1444 + 1444] = s_turn[lb];    // = lb*1805 + 1444 + (w - 361*lb)
    }
}

extern "C" void kernel_launch(void* const* d_in, const int* in_sizes, int n_in,
                              void* d_out, int out_size)
{
    const float* stones     = (const float*)d_in[0];
    const int*   cur_player = (const int*)  d_in[1];
    const int*   ko_points  = (const int*)  d_in[2];
    float*       out        = (float*)      d_out;

    const int B = in_sizes[1];                      // current_player has B elements
    const int grid = (B + BPB - 1) / BPB;
    go_feat_kernel<<<grid, NT>>>(stones, cur_player, ko_points, out, B);
}

// round 5
// speedup vs baseline: 1.0364x; 1.0364x over previous
#include <cuda_runtime.h>
#include <cstdint>

#define HH 19
#define CELLS 361
#define MASK19 0x7FFFFu
#define BPB 4
#define NT 384                           // 12 warps
#define NGROUP 1805                      // float4 groups per block (7220/4)
#define NBITW 97                         // 96 ballot words + 1 pad

__device__ uint32_t g_desc[NGROUP];

// desc: kind[0:2] (0=binary,1=lib,2=turn,3=slow), lb[2:4], sid[4:7], cell[7:16]
__global__ void init_desc_kernel()
{
    const int g = blockIdx.x * blockDim.x + threadIdx.x;
    if (g >= NGROUP) return;
    const int off  = 4 * g;
    const int lb   = off / 1805;
    const int rem  = off - 1805 * lb;
    const int ch   = rem / 361;
    const int cell = rem - 361 * ch;
    const int off3 = off + 3;
    const int lb2  = off3 / 1805;
    const int ch2  = (off3 - 1805 * lb2) / 361;
    uint32_t d;
    if (lb != lb2 || ch != ch2) d = 3u;                       // crosses boundary
    else if (ch == 4)           d = 2u | ((uint32_t)lb << 2);
    else if (ch == 3)           d = 1u | ((uint32_t)lb << 2) | (3u << 4)
                                       | ((uint32_t)cell << 7);
    else                        d = 0u | ((uint32_t)lb << 2) | ((uint32_t)ch << 4)
                                       | ((uint32_t)cell << 7);
    g_desc[g] = d;
}

// streams: per board 6 streams (0=cur,1=opp,2=legal,3=b0,4=b1,5=b2), 13 words each
#define STR(lb, sid) (((lb) * 6 + (sid)) * 13)

__device__ __forceinline__ uint32_t getbit(const uint32_t* s, int base, int cell) {
    return (s[base + (cell >> 5)] >> (cell & 31)) & 1u;
}

__global__ __launch_bounds__(NT)
void go_feat_kernel(const float* __restrict__ stones,
                    const int*   __restrict__ cur_player,
                    const int*   __restrict__ ko_points,
                    float*       __restrict__ out,
                    int B)
{
    __shared__ uint32_t s_bits[NBITW];            // input bitstream (block chunk)
    __shared__ uint32_t s_cur [BPB][21];          // padded row masks
    __shared__ uint32_t s_opp [BPB][21];
    __shared__ uint32_t s_emp [BPB][21];
    __shared__ uint32_t s_weak[BPB][21];
    __shared__ uint32_t s_rm[4][BPB][HH];         // legal,b0,b1,b2 row masks
    __shared__ uint32_t s_str[BPB * 6 * 13];      // channel bitstreams (+pad word)
    __shared__ float4   s_lut[48];                // 16 x(1.0) | 16 x(2.0) | 16 x(4.0)
    __shared__ int      s_cp[BPB];
    __shared__ float    s_turn[BPB];
    __shared__ int      s_ko[BPB][2];

    const int t     = threadIdx.x;
    const int bbase = blockIdx.x * BPB;
    const int rb    = (B - bbase) < BPB ? (B - bbase) : BPB;
    const int nin   = rb * 722;

    // ---- preload per-board scalars + build LUTs ----
    if (t < BPB) {
        const bool ok = t < rb;
        const int  b  = bbase + (ok ? t : 0);
        const int  cp = ok ? cur_player[b] : 0;
        s_cp[t]    = cp;
        s_turn[t]  = (float)cp;
        s_ko[t][0] = ok ? ko_points[2 * b]     : -1;
        s_ko[t][1] = ok ? ko_points[2 * b + 1] : 0;
    }
    if (t < 192) {                                 // one float each
        const int tab  = t >> 6;                   // 0,1,2
        const int idx  = (t & 63) >> 2;            // nibble 0..15
        const int comp = t & 3;
        const float sc = (float)(1 << tab);
        ((float*)s_lut)[t] = ((idx >> comp) & 1) ? sc : 0.0f;
    }
    if (t == 0) s_bits[96] = 0u;

    // ---- Phase A: ballot-pack the input into a 2888-bit stream ----
    const float* src = stones + (size_t)bbase * 722;
#pragma unroll
    for (int k = 0; k < 8; ++k) {                  // 8*384 = 3072 >= 2888
        const int i = k * NT + t;
        const bool act = i < nin;
        float v = 0.0f;
        if (act) v = src[i];
        const unsigned bal = __ballot_sync(0xFFFFFFFFu, act && (v > 0.5f));
        if ((t & 31) == 0)
            s_bits[k * 12 + (t >> 5)] = bal;       // i/32 == k*12 + warp
    }
    __syncthreads();

    // ---- Phase 1: row masks via funnel shift ----
    if (t < BPB * HH) {                            // 76 threads
        const int lb = t / HH, r = t % HH;
        if (lb < rb) {
            const int bit0 = lb * 722 + r * HH;
            const int bit1 = bit0 + 361;
            const uint32_t m0 = __funnelshift_r(s_bits[bit0 >> 5],
                                                s_bits[(bit0 >> 5) + 1],
                                                bit0 & 31) & MASK19;
            const uint32_t m1 = __funnelshift_r(s_bits[bit1 >> 5],
                                                s_bits[(bit1 >> 5) + 1],
                                                bit1 & 31) & MASK19;
            const int cp = s_cp[lb];
            s_cur[lb][r + 1] = cp ? m1 : m0;
            s_opp[lb][r + 1] = cp ? m0 : m1;
            s_emp[lb][r + 1] = (~(m0 | m1)) & MASK19;
            if (r == 0) {
                s_cur [lb][0] = 0u; s_cur [lb][20] = 0u;
                s_opp [lb][0] = 0u; s_opp [lb][20] = 0u;
                s_emp [lb][0] = 0u; s_emp [lb][20] = 0u;
                s_weak[lb][0] = 0u; s_weak[lb][20] = 0u;
            }
        }
    }
    __syncthreads();

    // ---- Phase 2: weak = opp with exactly one opp neighbor ----
    if (t < BPB * HH) {
        const int lb = t / HH, r = t % HH;
        if (lb < rb) {
            const uint32_t o   = s_opp[lb][r + 1];
            const uint32_t ou  = s_opp[lb][r];
            const uint32_t od  = s_opp[lb][r + 2];
            const uint32_t ol  = (o << 1) & MASK19;
            const uint32_t orr = o >> 1;
            const uint32_t par = ou ^ od ^ ol ^ orr;
            const uint32_t ge2 = (ou & od) | (ol & orr) | ((ou | od) & (ol | orr));
            s_weak[lb][r + 1] = o & par & ~ge2;
        }
    }
    __syncthreads();

    // ---- Phase 3: legal row masks + liberty bitplanes ----
    if (t < 2 * BPB * HH) {                        // 152 threads
        const int half = t / (BPB * HH);
        const int w  = t % (BPB * HH);
        const int lb = w / HH, r = w % HH;
        if (lb < rb) {
            if (half == 0) {
                const uint32_t empb = s_emp[lb][r + 1];
                const uint32_t eu = s_emp [lb][r], ed = s_emp [lb][r + 2];
                const uint32_t wk = s_weak[lb][r + 1];
                const uint32_t wu = s_weak[lb][r], wd = s_weak[lb][r + 2];
                const uint32_t nbr = eu | ed | ((empb << 1) & MASK19) | (empb >> 1)
                                   | wu | wd | ((wk  << 1) & MASK19) | (wk  >> 1);
                uint32_t legal = empb & nbr;
                const int kr = s_ko[lb][0];
                if (kr >= 0) {
                    const int rr = kr > (HH - 1) ? (HH - 1) : kr;
                    int cc = s_ko[lb][1];
                    cc = cc < 0 ? 0 : (cc > (HH - 1) ? (HH - 1) : cc);
                    if (rr == r) legal &= ~(1u << cc);
                }
                s_rm[0][lb][r] = legal;
            } else {
                const uint32_t curb = s_cur[lb][r + 1];
                const uint32_t cu   = s_cur[lb][r];
                const uint32_t cd   = s_cur[lb][r + 2];
                const uint32_t cl   = (curb << 1) & MASK19;
                const uint32_t crr  = curb >> 1;
                const uint32_t empb = s_emp[lb][r + 1];
                const uint32_t sab = cu ^ cd,  cab = cu & cd;
                const uint32_t scd = cl ^ crr, ccd = cl & crr;
                const uint32_t kk  = sab & scd;
                s_rm[1][lb][r] = (sab ^ scd)      & empb;   // ones
                s_rm[2][lb][r] = (cab ^ ccd ^ kk) & empb;   // twos
                s_rm[3][lb][r] = (cab & ccd)      & empb;   // fours
            }
        }
    }
    __syncthreads();

    // ---- Phase 3.5: assemble 361-bit channel streams ----
    if (t < 96) {
        // cur/opp: direct funnel re-slice of the input bitstream
        const int lb  = t / 24;
        const int sid = (t % 24) / 12;             // 0=cur,1=opp
        const int w   = t % 12;
        const int cp  = s_cp[lb];
        const int pl  = (sid == 0) ? cp : (1 - cp);
        const int base = lb * 722 + pl * 361 + 32 * w;
        uint32_t v = __funnelshift_r(s_bits[base >> 5], s_bits[(base >> 5) + 1],
                                     base & 31);
        if (w == 11) v &= 0x1FFu;                  // bits beyond 360 are garbage
        s_str[STR(lb, sid) + w] = v;
    } else if (t < 288) {
        // legal/b0/b1/b2: gather row masks into stream words
        const int u   = t - 96;                    // 0..191
        const int lb  = u / 48;
        const int sid = 2 + (u % 48) / 12;         // 2..5
        const int w   = u % 12;
        const uint32_t* rm = s_rm[sid - 2][lb];
        uint32_t v = 0u;
        int r = (32 * w) / HH;
#pragma unroll
        for (int it = 0; it < 3; ++it) {
            if (r < HH) {
                const int sh = HH * r - 32 * w;
                if (sh < 32) {
                    v |= (sh >= 0) ? (rm[r] << sh) : (rm[r] >> (-sh));
                    ++r;
                }
            }
        }
        s_str[STR(lb, sid) + w] = v;
    } else if (t < 312) {
        s_str[(t - 288) * 13 + 12] = 0u;           // pad word per stream
    }
    __syncthreads();

    // ---- Phase 4: expand to global, one float4 per group ----
    float4* outB = (float4*)(out + (size_t)bbase * 1805);
#pragma unroll
    for (int g = t; g < NGROUP; g += NT) {
        const uint32_t d    = g_desc[g];
        const uint32_t kind = d & 3u;
        const int      lb   = (d >> 2) & 3u;
        if (kind <= 1u) {
            if (lb >= rb) continue;
            const int sid  = (d >> 4) & 7u;
            const int cell = (d >> 7) & 0x1FFu;
            const int base = STR(lb, sid) + (cell >> 5);
            const int sh   = cell & 31;
            const uint32_t n0 = __funnelshift_r(s_str[base], s_str[base + 1], sh) & 0xFu;
            float4 val = s_lut[n0];
            if (kind == 1u) {
                const uint32_t n1 = __funnelshift_r(s_str[base + 13], s_str[base + 14], sh) & 0xFu;
                const uint32_t n2 = __funnelshift_r(s_str[base + 26], s_str[base + 27], sh) & 0xFu;
                const float4 v1 = s_lut[16 + n1];
                const float4 v2 = s_lut[32 + n2];
                val.x += v1.x + v2.x;
                val.y += v1.y + v2.y;
                val.z += v1.z + v2.z;
                val.w += v1.w + v2.w;
            }
            outB[g] = val;
        } else if (kind == 2u) {
            if (lb >= rb) continue;
            const float tv = s_turn[lb];
            outB[g] = make_float4(tv, tv, tv, tv);
        } else {
            // slow path: group straddles a channel/board boundary
            float* o = (float*)outB;
#pragma unroll
            for (int j = 0; j < 4; ++j) {
                const int off  = 4 * g + j;
                const int lbj  = off / 1805;
                const int rem  = off - 1805 * lbj;
                const int ch   = rem / 361;
                const int cell = rem - 361 * ch;
                if (lbj >= rb) continue;
                float v;
                if (ch == 4)      v = s_turn[lbj];
                else if (ch == 3) {
                    const uint32_t n = getbit(s_str, STR(lbj, 3), cell)
                                     + 2u * getbit(s_str, STR(lbj, 4), cell)
                                     + 4u * getbit(s_str, STR(lbj, 5), cell);
                    v = (float)n;
                } else {
                    v = getbit(s_str, STR(lbj, ch), cell) ? 1.0f : 0.0f;
                }
                o[off] = v;
            }
        }
    }
}

extern "C" void kernel_launch(void* const* d_in, const int* in_sizes, int n_in,
                              void* d_out, int out_size)
{
    const float* stones     = (const float*)d_in[0];
    const int*   cur_player = (const int*)  d_in[1];
    const int*   ko_points  = (const int*)  d_in[2];
    float*       out        = (float*)      d_out;

    const int B = in_sizes[1];                     // current_player has B elements
    init_desc_kernel<<<(NGROUP + 255) / 256, 256>>>();
    const int grid = (B + BPB - 1) / BPB;
    go_feat_kernel<<<grid, NT>>>(stones, cur_player, ko_points, out, B);
}

// round 6
// speedup vs baseline: 1.1435x; 1.1034x over previous
#include <cuda_runtime.h>
#include <cstdint>

#define HH 19
#define CELLS 361
#define MASK19 0x7FFFFu
#define BPB 8
#define NT 640                // 20 warps
#define NWARP 20
#define NBITW 201             // ballot words (max idx 199) + funnel pad

// weak = opp stone with exactly one orthogonal opp neighbor (rows om=self, ou=above, od=below)
__device__ __forceinline__ uint32_t weak_row(uint32_t om, uint32_t ou, uint32_t od) {
    const uint32_t ol  = (om << 1) & MASK19;
    const uint32_t orr = om >> 1;
    const uint32_t par = ou ^ od ^ ol ^ orr;
    const uint32_t ge2 = (ou & od) | (ol & orr) | ((ou | od) & (ol | orr));
    return om & par & ~ge2;
}

// aligned 32-bit word w (bits [32w,32w+32)) of the 361-bit stream formed by 19 row masks
__device__ __forceinline__ uint32_t gather_word(const uint32_t* rm, int w) {
    uint32_t v = 0u;
    int r = (32 * w) / HH;
#pragma unroll
    for (int it = 0; it < 3; ++it) {
        if (r < HH) {
            const int sh = HH * r - 32 * w;
            if (sh < 32) {
                v |= (sh >= 0) ? (rm[r] << sh) : (rm[r] >> (-sh));
                ++r;
            }
        }
    }
    return v;
}

__global__ __launch_bounds__(NT)
void go_feat_kernel(const float* __restrict__ stones,
                    const int*   __restrict__ cur_player,
                    const int*   __restrict__ ko_points,
                    float*       __restrict__ out,
                    int B)
{
    __shared__ uint32_t s_bits[NBITW];        // input bitstream (8 boards * 722 bits)
    __shared__ uint32_t s_cur[BPB][23];       // pad-2 row masks (real rows at [2..20])
    __shared__ uint32_t s_opp[BPB][23];
    __shared__ uint32_t s_emp[BPB][23];
    __shared__ uint32_t s_rm[4][BPB][HH];     // 0=legal, 1=b0, 2=b1, 3=b2
    __shared__ int      s_cp[BPB];
    __shared__ float    s_turn[BPB];
    __shared__ int      s_ko[BPB][2];

    const int t     = threadIdx.x;
    const int bbase = blockIdx.x * BPB;
    const int rb    = (B - bbase) < BPB ? (B - bbase) : BPB;
    const int nin   = rb * 722;

    // ---- per-board scalars ----
    if (t < BPB) {
        const bool ok = t < rb;
        const int  b  = bbase + (ok ? t : 0);
        const int  cp = ok ? cur_player[b] : 0;
        s_cp[t]    = cp;
        s_turn[t]  = (float)cp;
        s_ko[t][0] = ok ? ko_points[2 * b]     : -1;
        s_ko[t][1] = ok ? ko_points[2 * b + 1] : 0;
    }

    // ---- Phase A: ballot-pack the input into a bitstream ----
    const float* src = stones + (size_t)bbase * 722;
#pragma unroll
    for (int k = 0; k < 10; ++k) {            // 10*640 = 6400 >= 5776
        const int i = k * NT + t;
        const bool act = i < nin;
        float v = 0.0f;
        if (act) v = src[i];
        const unsigned bal = __ballot_sync(0xFFFFFFFFu, act && (v > 0.5f));
        if ((t & 31) == 0)
            s_bits[k * NWARP + (t >> 5)] = bal;   // i/32 = k*20 + warp
    }
    __syncthreads();

    // ---- Phase 1: row masks (funnel-slice of bitstream) ----
    if (t < BPB * HH) {                       // 152 threads
        const int lb = t / HH, r = t % HH;
        const int bit0 = lb * 722 + r * HH;
        const int bit1 = bit0 + 361;
        const uint32_t m0 = __funnelshift_r(s_bits[bit0 >> 5],
                                            s_bits[(bit0 >> 5) + 1],
                                            bit0 & 31) & MASK19;
        const uint32_t m1 = __funnelshift_r(s_bits[bit1 >> 5],
                                            s_bits[(bit1 >> 5) + 1],
                                            bit1 & 31) & MASK19;
        const int cp = s_cp[lb];
        s_cur[lb][r + 2] = cp ? m1 : m0;
        s_opp[lb][r + 2] = cp ? m0 : m1;
        s_emp[lb][r + 2] = (~(m0 | m1)) & MASK19;
        if (r == 0) {
            s_cur[lb][0] = 0u; s_cur[lb][1] = 0u; s_cur[lb][21] = 0u; s_cur[lb][22] = 0u;
            s_opp[lb][0] = 0u; s_opp[lb][1] = 0u; s_opp[lb][21] = 0u; s_opp[lb][22] = 0u;
            s_emp[lb][0] = 0u; s_emp[lb][1] = 0u; s_emp[lb][21] = 0u; s_emp[lb][22] = 0u;
        }
    }
    __syncthreads();

    // ---- Phase 3: legal row masks (weak inlined) + liberty bitplanes ----
    if (t < 2 * BPB * HH) {                   // 304 threads
        const int half = t / (BPB * HH);
        const int w    = t % (BPB * HH);
        const int lb   = w / HH, r = w % HH;
        if (half == 0) {
            const uint32_t* op = s_opp[lb];
            const uint32_t wkm = weak_row(op[r + 2], op[r + 1], op[r + 3]); // wk(r)
            const uint32_t wku = weak_row(op[r + 1], op[r],     op[r + 2]); // wk(r-1)
            const uint32_t wkd = weak_row(op[r + 3], op[r + 2], op[r + 4]); // wk(r+1)
            const uint32_t empb = s_emp[lb][r + 2];
            const uint32_t eu = s_emp[lb][r + 1], ed = s_emp[lb][r + 3];
            const uint32_t nbr = eu | ed | ((empb << 1) & MASK19) | (empb >> 1)
                               | wku | wkd | ((wkm << 1) & MASK19) | (wkm >> 1);
            uint32_t legal = empb & nbr;
            const int kr = s_ko[lb][0];
            if (kr >= 0) {
                const int rr = kr > (HH - 1) ? (HH - 1) : kr;
                int cc = s_ko[lb][1];
                cc = cc < 0 ? 0 : (cc > (HH - 1) ? (HH - 1) : cc);
                if (rr == r) legal &= ~(1u << cc);
            }
            s_rm[0][lb][r] = legal;
        } else {
            const uint32_t curb = s_cur[lb][r + 2];
            const uint32_t cu   = s_cur[lb][r + 1];
            const uint32_t cd   = s_cur[lb][r + 3];
            const uint32_t cl   = (curb << 1) & MASK19;
            const uint32_t crr  = curb >> 1;
            const uint32_t empb = s_emp[lb][r + 2];
            const uint32_t sab = cu ^ cd,  cab = cu & cd;
            const uint32_t scd = cl ^ crr, ccd = cl & crr;
            const uint32_t kk  = sab & scd;
            s_rm[1][lb][r] = (sab ^ scd)      & empb;   // ones
            s_rm[2][lb][r] = (cab ^ ccd ^ kk) & empb;   // twos
            s_rm[3][lb][r] = (cab & ccd)      & empb;   // fours
        }
    }
    __syncthreads();

    // ---- Phase 4: warp-per-(board,channel) expansion, shfl word broadcast ----
    const int warp = t >> 5, lane = t & 31;
    float* outb = out + (size_t)bbase * 1805;
#pragma unroll
    for (int u = warp; u < 5 * BPB; u += NWARP) {     // exactly 2 units per warp
        const int lb = u / 5;
        const int ch = u - 5 * lb;
        if (lb >= rb) continue;                        // warp-uniform
        float* o = outb + (size_t)lb * 1805 + ch * CELLS;

        if (ch == 4) {
            const float tv = s_turn[lb];
#pragma unroll
            for (int it = 0; it < 12; ++it) {
                const int idx = it * 32 + lane;
                if (idx < CELLS) o[idx] = tv;
            }
        } else if (ch == 3) {
            uint32_t w0 = 0u, w1 = 0u, w2 = 0u;
            if (lane < 12) {
                w0 = gather_word(s_rm[1][lb], lane);
                w1 = gather_word(s_rm[2][lb], lane);
                w2 = gather_word(s_rm[3][lb], lane);
            }
#pragma unroll
            for (int it = 0; it < 12; ++it) {
                const uint32_t a = __shfl_sync(0xFFFFFFFFu, w0, it);
                const uint32_t b = __shfl_sync(0xFFFFFFFFu, w1, it);
                const uint32_t c = __shfl_sync(0xFFFFFFFFu, w2, it);
                const int idx = it * 32 + lane;
                const uint32_t n = ((a >> lane) & 1u)
                                 | (((b >> lane) & 1u) << 1)
                                 | (((c >> lane) & 1u) << 2);
                if (idx < CELLS) o[idx] = (float)n;
            }
        } else {
            uint32_t myw = 0u;
            if (lane < 12) {
                if (ch == 2) {
                    myw = gather_word(s_rm[0][lb], lane);
                } else {
                    const int pl   = (ch == 0) ? s_cp[lb] : 1 - s_cp[lb];
                    const int base = lb * 722 + pl * CELLS + 32 * lane;
                    myw = __funnelshift_r(s_bits[base >> 5],
                                          s_bits[(base >> 5) + 1],
                                          base & 31);
                }
            }
#pragma unroll
            for (int it = 0; it < 12; ++it) {
                const uint32_t w = __shfl_sync(0xFFFFFFFFu, myw, it);
                const int idx = it * 32 + lane;
                if (idx < CELLS) o[idx] = (float)((w >> lane) & 1u);
            }
        }
    }
}

extern "C" void kernel_launch(void* const* d_in, const int* in_sizes, int n_in,
                              void* d_out, int out_size)
{
    const float* stones     = (const float*)d_in[0];
    const int*   cur_player = (const int*)  d_in[1];
    const int*   ko_points  = (const int*)  d_in[2];
    float*       out        = (float*)      d_out;

    const int B = in_sizes[1];                 // current_player has B elements
    const int grid = (B + BPB - 1) / BPB;
    go_feat_kernel<<<grid, NT>>>(stones, cur_player, ko_points, out, B);
}